// round 8
// baseline (speedup 1.0000x reference)
#include <cuda_runtime.h>
#include <cstdint>

#define B_ 64
#define Q_ 900
#define T_ 100
#define C_ 256
#define NTC 256          // cost kernel block
#define NTH 512          // hungarian block
#define K_ 2             // columns per hungarian thread: NTH*K_ >= Q_
#define NW (NTH / 32)

// Scratch: transposed cost [B, T, Q] so hungarian reads contiguous rows.
__device__ float g_costT[(size_t)B_ * T_ * Q_];
// Per-(b,t) ~packed row-min key; 0 (static init) is the identity for atomicMax.
__device__ unsigned long long g_rowmin[B_ * T_];   // zero-initialized

__device__ __forceinline__ unsigned order_f(float f) {
    unsigned o = __float_as_uint(f);
    return (o & 0x80000000u) ? ~o : (o | 0x80000000u);
}
__device__ __forceinline__ float unorder_f(unsigned o) {
    return __uint_as_float((o & 0x80000000u) ? (o ^ 0x80000000u) : ~o);
}

// explicit 4-level min tree over NW u64 smem entries
__device__ __forceinline__ unsigned long long tree_min16(
        const unsigned long long* a) {
    unsigned long long t0 = a[0] < a[8] ? a[0] : a[8];
    unsigned long long t1 = a[1] < a[9] ? a[1] : a[9];
    unsigned long long t2 = a[2] < a[10] ? a[2] : a[10];
    unsigned long long t3 = a[3] < a[11] ? a[3] : a[11];
    unsigned long long t4 = a[4] < a[12] ? a[4] : a[12];
    unsigned long long t5 = a[5] < a[13] ? a[5] : a[13];
    unsigned long long t6 = a[6] < a[14] ? a[6] : a[14];
    unsigned long long t7 = a[7] < a[15] ? a[7] : a[15];
    t0 = t0 < t4 ? t0 : t4;  t1 = t1 < t5 ? t1 : t5;
    t2 = t2 < t6 ? t2 : t6;  t3 = t3 < t7 ? t3 : t7;
    t0 = t0 < t2 ? t0 : t2;  t1 = t1 < t3 ? t1 : t3;
    return t0 < t1 ? t0 : t1;
}

// ---------------------------------------------------------------------------
// Kernel 1 (R6 version): one block per (b, 32-query tile). Label-sorted
// target order makes the logits gather semi-coalesced.
// ---------------------------------------------------------------------------
__global__ void __launch_bounds__(NTC) cost_fused_kernel(
        const float* __restrict__ logits,
        const float* __restrict__ pboxes,
        const int* __restrict__ labels,
        const float* __restrict__ tboxes,
        float* __restrict__ out) {
    __shared__ int    lab_s[T_];
    __shared__ int    ord_s[T_];      // targets sorted by (label, t)
    __shared__ float4 tb_s[T_];
    __shared__ float4 pb_s[32];
    __shared__ float  tile[32][101];  // [q_in_tile][t]

    int b = blockIdx.y;
    int q0 = blockIdx.x * 32;
    int tid = threadIdx.x;

    if (tid < T_) {
        int lab = labels[b * T_ + tid];
        lab_s[tid] = lab;
        tb_s[tid] = __ldg(&((const float4*)tboxes)[b * T_ + tid]);
    }
    if (tid < 32 && q0 + tid < Q_)
        pb_s[tid] = __ldg(&((const float4*)pboxes)[b * Q_ + q0 + tid]);
    __syncthreads();

    if (tid < T_) {                   // rank sort by (label, index)
        int lab = lab_s[tid];
        int rank = 0;
        for (int s = 0; s < T_; s++) {
            int ls = lab_s[s];
            rank += (ls < lab) || (ls == lab && s < tid);
        }
        ord_s[rank] = tid;
    }
    __syncthreads();

    int qq = tid >> 3;                // 0..31
    int q = q0 + qq;
    int t_lo = tid & 7;               // 0..7
    if (q < Q_) {
        float4 pb = pb_s[qq];
        float ax0 = pb.x - 0.5f * pb.z, ay0 = pb.y - 0.5f * pb.w;
        float ax1 = pb.x + 0.5f * pb.z, ay1 = pb.y + 0.5f * pb.w;
        float areaA = (ax1 - ax0) * (ay1 - ay0);
        const float* lrow = logits + ((long long)b * Q_ + q) * C_;

        #pragma unroll
        for (int s = 0; s < 13; s++) {
            int sidx = t_lo + (s << 3);
            if (sidx >= T_) break;
            int tt = ord_s[sidx];     // label-sorted order -> coalesced gather

            float cc = -__ldg(lrow + lab_s[tt]);
            float4 tb = tb_s[tt];

            float cb = fabsf(pb.x - tb.x) + fabsf(pb.y - tb.y);
            cb += fabsf(pb.z - tb.z);
            cb += fabsf(pb.w - tb.w);

            float bx0 = tb.x - 0.5f * tb.z, by0 = tb.y - 0.5f * tb.w;
            float bx1 = tb.x + 0.5f * tb.z, by1 = tb.y + 0.5f * tb.w;

            float areaB = (bx1 - bx0) * (by1 - by0);
            float wx = fminf(ax1, bx1) - fmaxf(ax0, bx0); wx = fmaxf(wx, 0.f);
            float wy = fminf(ay1, by1) - fmaxf(ay0, by0); wy = fmaxf(wy, 0.f);
            float inter = wx * wy;
            float uni = areaA + areaB - inter;
            float iou = inter / uni;
            float ex = fmaxf(ax1, bx1) - fminf(ax0, bx0); ex = fmaxf(ex, 0.f);
            float ey = fmaxf(ay1, by1) - fminf(ay0, by0); ey = fmaxf(ey, 0.f);
            float enc = ex * ey;
            float giou = iou - (enc - uni) / enc;

            tile[qq][tt] = (cc + cb) - giou;
        }
    }
    __syncthreads();

    for (int idx = tid; idx < 32 * T_; idx += NTC) {
        int qq2 = idx / T_, tt = idx - qq2 * T_;
        int q2 = q0 + qq2;
        if (q2 < Q_)
            out[((size_t)b * Q_ + q2) * T_ + tt] = tile[qq2][tt];
    }
    for (int idx = tid; idx < 32 * T_; idx += NTC) {
        int tt = idx >> 5, q2 = q0 + (idx & 31);
        if (q2 < Q_)
            g_costT[((size_t)b * T_ + tt) * Q_ + q2] = tile[idx & 31][tt];
    }
    if (tid < T_) {
        unsigned long long best = ~0ull;
        int qmax = min(32, Q_ - q0);
        for (int k = 0; k < qmax; k++) {
            unsigned long long key =
                ((unsigned long long)order_f(tile[k][tid]) << 32) | (unsigned)(q0 + k);
            if (key < best) best = key;
        }
        atomicMax(&g_rowmin[b * T_ + tid], ~best);
    }
}

// ---------------------------------------------------------------------------
// Kernel 2: JV = greedy init + single-pass ARR (two-smallest) + SAP.
// One CTA (512 threads, K=2 cols/thread) per batch.
// ---------------------------------------------------------------------------
__global__ void __launch_bounds__(NTH) hungarian_kernel(float* __restrict__ out,
                                                        int writeIdx) {
    int b = blockIdx.x;
    const float* cost = g_costT + (size_t)b * T_ * Q_;

    __shared__ float u[T_ + 1];
    __shared__ int p[Q_];                 // row matched to col j (-1 free)
    __shared__ int sway[Q_];              // predecessor column
    __shared__ unsigned long long wred[2][NW];
    __shared__ unsigned wred2[2][NW];
    __shared__ int colarr[T_];
    __shared__ int argj[T_];
    __shared__ int rowmatch[T_];
    __shared__ int flist[T_];
    __shared__ int nfree_s;

    int tid = threadIdx.x;
    int lane = tid & 31, wid = tid >> 5;

    float vreg[K_];
    #pragma unroll
    for (int k = 0; k < K_; k++) vreg[k] = 0.f;

    for (int j = tid; j < Q_; j += NTH) p[j] = -1;
    if (tid == 0) u[T_] = 0.f;

    // ---- Phase 0: greedy duals from precomputed row-mins ----
    if (tid < T_) {
        unsigned long long key = ~g_rowmin[b * T_ + tid];
        argj[tid] = (int)(key & 0xFFFFFFFFu);
        u[tid] = unorder_f((unsigned)(key >> 32));
    }
    __syncthreads();

    if (tid == 0) {
        int nf = 0;
        for (int i = 0; i < T_; i++) {
            int j = argj[i];
            if (p[j] < 0) { p[j] = i; rowmatch[i] = 1; }
            else { rowmatch[i] = 0; flist[nf++] = i; }
        }
        nfree_s = nf;
    }
    __syncthreads();

    // ---- Phase 0.5: augmenting row reduction (single reduction per scan) ----
    {
        int nf = nfree_s;
        int scans = 0;
        for (int f = 0; f < nf; f++) {
            int i = flist[f];
            while (i >= 0 && scans < 400) {
                const float* row = cost + (size_t)i * Q_;

                // per-thread two smallest over K=2 columns
                unsigned o0 = 0xFFFFFFFFu, o1 = 0xFFFFFFFFu;
                {
                    float c0 = __ldg(row + tid) - vreg[0];
                    o0 = order_f(c0);
                    int j2 = tid + NTH;
                    if (j2 < Q_) o1 = order_f(__ldg(row + j2) - vreg[1]);
                }
                unsigned lo, hi, bj;
                if (o0 <= o1) { lo = o0; hi = o1; bj = (unsigned)tid; }
                else          { lo = o1; hi = o0; bj = (unsigned)(tid + NTH); }

                unsigned m1w = __reduce_min_sync(0xFFFFFFFFu, lo);
                unsigned ball = __ballot_sync(0xFFFFFFFFu, lo == m1w);
                unsigned jc = (lo == m1w) ? bj : 0xFFFFFFFFu;
                unsigned j1w = __reduce_min_sync(0xFFFFFFFFu, jc);
                unsigned m2c = (lo == m1w) ? hi : lo;
                unsigned m2w = __reduce_min_sync(0xFFFFFFFFu, m2c);
                if (__popc(ball) > 1) m2w = m1w;

                int buf = scans & 1;
                if (lane == 0) {
                    wred[buf][wid] = ((unsigned long long)m1w << 32) | j1w;
                    wred2[buf][wid] = m2w;
                }
                __syncthreads();     // BAR-A: reductions visible

                unsigned long long tot = tree_min16(wred[buf]);
                int j1 = (int)(tot & 0xFFFFFFFFu);
                unsigned m1o = (unsigned)(tot >> 32);
                // global m2
                unsigned m2o = 0xFFFFFFFFu;
                int cnt = 0;
                #pragma unroll
                for (int w = 0; w < NW; w++) {
                    unsigned mw = (unsigned)(wred[buf][w] >> 32);
                    if (mw == m1o) {
                        cnt++;
                        unsigned x = wred2[buf][w];
                        if (x < m2o) m2o = x;
                    } else if (mw < m2o) {
                        m2o = mw;
                    }
                }
                if (cnt > 1) m2o = m1o;

                float m1 = unorder_f(m1o);
                float m2 = unorder_f(m2o);
                int iold = p[j1];
                bool take = (iold < 0) || (m1o < m2o);
                __syncthreads();     // BAR-B: all read p[j1] before writes

                if (take) {
                    if ((j1 & (NTH - 1)) == tid)
                        vreg[j1 >> 9] -= (m2 - m1);      // keeps (i,j1) tight
                    if (tid == 0) {
                        u[i] = m2;
                        p[j1] = i;
                        rowmatch[i] = 1;
                        if (iold >= 0) rowmatch[iold] = 0;
                    }
                    i = iold;                            // continue chain (-1 if free)
                } else {
                    if (tid == 0) u[i] = m2;             // m1 == m2, still feasible
                    i = -1;                              // leave for SAP
                }
                scans++;
            }
        }
        __syncthreads();
    }

    // ---- Phase 1: shortest augmenting path for remaining unmatched rows ----
    for (int i = 0; i < T_; i++) {
        if (rowmatch[i]) continue;

        unsigned minv[K_];                 // ordered-uint shortest-path dist
        unsigned um = 0;
        #pragma unroll
        for (int k = 0; k < K_; k++) {
            minv[k] = 0xFFFFFFFEu;
            if (tid + k * NTH >= Q_) um |= (1u << k);
        }

        int j0 = Q_;
        int i0 = i;
        float shift = 0.f;
        int iter = 0;
        int j1;
        float Sf;
        unsigned Sfo;

        while (true) {
            float base = shift - u[i0];
            const float* row = cost + (size_t)i0 * Q_;

            unsigned bo = 0xFFFFFFFFu, bj = 0xFFFFFFFFu;
            #pragma unroll
            for (int k = 0; k < K_; k++) {
                int j = tid + k * NTH;
                if (!((um >> k) & 1u)) {
                    unsigned co = order_f(__ldg(row + j) - vreg[k] + base);
                    if (co < minv[k]) { minv[k] = co; sway[j] = j0; }
                    if (minv[k] < bo) { bo = minv[k]; bj = (unsigned)j; }
                }
            }
            unsigned m = __reduce_min_sync(0xFFFFFFFFu, bo);
            unsigned jc = (bo == m) ? bj : 0xFFFFFFFFu;
            unsigned jm = __reduce_min_sync(0xFFFFFFFFu, jc);

            int buf = iter & 1;
            if (lane == 0)
                wred[buf][wid] = ((unsigned long long)m << 32) | jm;
            __syncthreads();

            unsigned long long tot = tree_min16(wred[buf]);
            j1 = (int)(tot & 0xFFFFFFFFu);
            Sfo = (unsigned)(tot >> 32);
            Sf = unorder_f(Sfo);

            int i0n = p[j1];
            if (i0n < 0) break;

            if ((j1 & (NTH - 1)) == tid) um |= (1u << (j1 >> 9));
            j0 = j1;
            i0 = i0n;
            shift = Sf;
            iter++;
        }

        // deferred dual updates
        #pragma unroll
        for (int k = 0; k < K_; k++) {
            int j = tid + k * NTH;
            if (j < Q_ && ((um >> k) & 1u)) {
                float diff = Sf - unorder_f(minv[k]);
                vreg[k] -= diff;
                u[p[j]] += diff;
            }
        }
        if (tid == 0) u[i] += Sf;
        __syncthreads();

        if (tid == 0) {
            int j = j1;
            while (j != Q_) {
                int jn = sway[j];
                p[j] = (jn == Q_) ? i : p[jn];
                j = jn;
            }
            rowmatch[i] = 1;
        }
        __syncthreads();
    }

    // write indices sorted by query (rank via counting)
    for (int j = tid; j < Q_; j += NTH) {
        int r = p[j];
        if (r >= 0) colarr[r] = j;
    }
    __syncthreads();

    if (writeIdx) {
        float* oidx = out + (size_t)B_ * Q_ * T_;
        if (tid < T_) {
            int c = colarr[tid];
            int rank = 0;
            for (int s = 0; s < T_; s++) rank += (colarr[s] < c);
            oidx[(size_t)b * T_ + rank] = (float)c;                      // pred_idx
            oidx[(size_t)B_ * T_ + (size_t)b * T_ + rank] = (float)tid;  // tgt_idx
        }
    }

    // reset rowmin identity for the next graph replay
    if (tid < T_) g_rowmin[b * T_ + tid] = 0ull;
}

// ---------------------------------------------------------------------------
extern "C" void kernel_launch(void* const* d_in, const int* in_sizes, int n_in,
                              void* d_out, int out_size) {
    const float* logits = (const float*)d_in[0];
    const float* pboxes = (const float*)d_in[1];
    const int*   labels = (const int*)d_in[2];
    const float* tboxes = (const float*)d_in[3];
    float* out = (float*)d_out;

    dim3 tg((Q_ + 31) / 32, B_);
    cost_fused_kernel<<<tg, NTC>>>(logits, pboxes, labels, tboxes, out);

    int writeIdx = (out_size >= (int)((long long)B_ * Q_ * T_ + 2LL * B_ * T_)) ? 1 : 0;
    hungarian_kernel<<<B_, NTH>>>(out, writeIdx);
}

// round 9
// speedup vs baseline: 1.1216x; 1.1216x over previous
#include <cuda_runtime.h>
#include <cstdint>

#define B_ 64
#define Q_ 900
#define T_ 100
#define C_ 256
#define NTC 256          // cost kernel block
#define NTH 512          // hungarian block
#define K_ 2             // columns per hungarian thread: NTH*K_ >= Q_
#define NW (NTH / 32)

// Scratch: transposed cost [B, T, Q] so hungarian reads contiguous rows.
__device__ float g_costT[(size_t)B_ * T_ * Q_];
// Per-(b,t) ~packed row-min key; 0 (static init) is the identity for atomicMax.
__device__ unsigned long long g_rowmin[B_ * T_];   // zero-initialized

__device__ __forceinline__ unsigned order_f(float f) {
    unsigned o = __float_as_uint(f);
    return (o & 0x80000000u) ? ~o : (o | 0x80000000u);
}
__device__ __forceinline__ float unorder_f(unsigned o) {
    return __uint_as_float((o & 0x80000000u) ? (o ^ 0x80000000u) : ~o);
}

// explicit 4-level min tree over 16 u64 smem entries
__device__ __forceinline__ unsigned long long tree_min16(
        const unsigned long long* a) {
    unsigned long long t0 = a[0] < a[8] ? a[0] : a[8];
    unsigned long long t1 = a[1] < a[9] ? a[1] : a[9];
    unsigned long long t2 = a[2] < a[10] ? a[2] : a[10];
    unsigned long long t3 = a[3] < a[11] ? a[3] : a[11];
    unsigned long long t4 = a[4] < a[12] ? a[4] : a[12];
    unsigned long long t5 = a[5] < a[13] ? a[5] : a[13];
    unsigned long long t6 = a[6] < a[14] ? a[6] : a[14];
    unsigned long long t7 = a[7] < a[15] ? a[7] : a[15];
    t0 = t0 < t4 ? t0 : t4;  t1 = t1 < t5 ? t1 : t5;
    t2 = t2 < t6 ? t2 : t6;  t3 = t3 < t7 ? t3 : t7;
    t0 = t0 < t2 ? t0 : t2;  t1 = t1 < t3 ? t1 : t3;
    return t0 < t1 ? t0 : t1;
}

// ---------------------------------------------------------------------------
// Kernel 1: one block per (b, 32-query tile). Label-sorted target order makes
// the logits gather semi-coalesced. Per-target xyxy/area precomputed in smem.
// ---------------------------------------------------------------------------
__global__ void __launch_bounds__(NTC) cost_fused_kernel(
        const float* __restrict__ logits,
        const float* __restrict__ pboxes,
        const int* __restrict__ labels,
        const float* __restrict__ tboxes,
        float* __restrict__ out) {
    __shared__ int    lab_s[T_];
    __shared__ int    ord_s[T_];      // targets sorted by (label, t)
    __shared__ float4 tb_s[T_];       // cxcywh
    __shared__ float4 te_s[T_];       // xyxy
    __shared__ float  ta_s[T_];       // area
    __shared__ float4 pb_s[32];
    __shared__ float  tile[32][101];  // [q_in_tile][t]

    int b = blockIdx.y;
    int q0 = blockIdx.x * 32;
    int tid = threadIdx.x;

    if (tid < T_) {
        lab_s[tid] = labels[b * T_ + tid];
        float4 tb = __ldg(&((const float4*)tboxes)[b * T_ + tid]);
        tb_s[tid] = tb;
        float4 te;
        te.x = tb.x - 0.5f * tb.z; te.y = tb.y - 0.5f * tb.w;
        te.z = tb.x + 0.5f * tb.z; te.w = tb.y + 0.5f * tb.w;
        te_s[tid] = te;
        ta_s[tid] = (te.z - te.x) * (te.w - te.y);
    }
    if (tid < 32 && q0 + tid < Q_)
        pb_s[tid] = __ldg(&((const float4*)pboxes)[b * Q_ + q0 + tid]);
    __syncthreads();

    if (tid < T_) {                   // rank sort by (label, index)
        int lab = lab_s[tid];
        int rank = 0;
        for (int s = 0; s < T_; s++) {
            int ls = lab_s[s];
            rank += (ls < lab) || (ls == lab && s < tid);
        }
        ord_s[rank] = tid;
    }
    __syncthreads();

    int qq = tid >> 3;                // 0..31
    int q = q0 + qq;
    int t_lo = tid & 7;               // 0..7
    if (q < Q_) {
        float4 pb = pb_s[qq];
        float ax0 = pb.x - 0.5f * pb.z, ay0 = pb.y - 0.5f * pb.w;
        float ax1 = pb.x + 0.5f * pb.z, ay1 = pb.y + 0.5f * pb.w;
        float areaA = (ax1 - ax0) * (ay1 - ay0);
        const float* lrow = logits + ((long long)b * Q_ + q) * C_;

        #pragma unroll
        for (int s = 0; s < 13; s++) {
            int sidx = t_lo + (s << 3);
            if (sidx >= T_) break;
            int tt = ord_s[sidx];     // label-sorted order -> coalesced gather

            float cc = -__ldg(lrow + lab_s[tt]);
            float4 tb = tb_s[tt];
            float4 te = te_s[tt];

            float cb = fabsf(pb.x - tb.x) + fabsf(pb.y - tb.y);
            cb += fabsf(pb.z - tb.z);
            cb += fabsf(pb.w - tb.w);

            float wx = fminf(ax1, te.z) - fmaxf(ax0, te.x); wx = fmaxf(wx, 0.f);
            float wy = fminf(ay1, te.w) - fmaxf(ay0, te.y); wy = fmaxf(wy, 0.f);
            float inter = wx * wy;
            float uni = areaA + ta_s[tt] - inter;
            float iou = __fdividef(inter, uni);
            float ex = fmaxf(ax1, te.z) - fminf(ax0, te.x); ex = fmaxf(ex, 0.f);
            float ey = fmaxf(ay1, te.w) - fminf(ay0, te.y); ey = fmaxf(ey, 0.f);
            float enc = ex * ey;
            float giou = iou - __fdividef(enc - uni, enc);

            tile[qq][tt] = (cc + cb) - giou;
        }
    }
    __syncthreads();

    for (int idx = tid; idx < 32 * T_; idx += NTC) {
        int qq2 = idx / T_, tt = idx - qq2 * T_;
        int q2 = q0 + qq2;
        if (q2 < Q_)
            out[((size_t)b * Q_ + q2) * T_ + tt] = tile[qq2][tt];
    }
    for (int idx = tid; idx < 32 * T_; idx += NTC) {
        int tt = idx >> 5, q2 = q0 + (idx & 31);
        if (q2 < Q_)
            g_costT[((size_t)b * T_ + tt) * Q_ + q2] = tile[idx & 31][tt];
    }
    if (tid < T_) {
        unsigned long long best = ~0ull;
        int qmax = min(32, Q_ - q0);
        for (int k = 0; k < qmax; k++) {
            unsigned long long key =
                ((unsigned long long)order_f(tile[k][tid]) << 32) | (unsigned)(q0 + k);
            if (key < best) best = key;
        }
        atomicMax(&g_rowmin[b * T_ + tid], ~best);
    }
}

// ---------------------------------------------------------------------------
// Kernel 2: JV = greedy init + ARR (tid0-owned state, 2 BAR/scan) + SAP.
// One CTA (512 threads, K=2 cols/thread) per batch.
// ---------------------------------------------------------------------------
__global__ void __launch_bounds__(NTH) hungarian_kernel(float* __restrict__ out,
                                                        int writeIdx) {
    int b = blockIdx.x;
    const float* cost = g_costT + (size_t)b * T_ * Q_;

    __shared__ float u[T_ + 1];
    __shared__ int p[Q_];                 // row matched to col j (-1 free)
    __shared__ int sway[Q_];              // predecessor column
    __shared__ unsigned long long wred[2][NW];
    __shared__ unsigned wred2[NW];
    __shared__ int colarr[T_];
    __shared__ int argj[T_];
    __shared__ int rowmatch[T_];
    __shared__ int flist[T_];
    __shared__ int nfree_s;
    __shared__ int inext_s;

    int tid = threadIdx.x;
    int lane = tid & 31, wid = tid >> 5;

    float vreg[K_];
    #pragma unroll
    for (int k = 0; k < K_; k++) vreg[k] = 0.f;

    for (int j = tid; j < Q_; j += NTH) p[j] = -1;
    if (tid == 0) u[T_] = 0.f;

    // ---- Phase 0: greedy duals from precomputed row-mins ----
    if (tid < T_) {
        unsigned long long key = ~g_rowmin[b * T_ + tid];
        argj[tid] = (int)(key & 0xFFFFFFFFu);
        u[tid] = unorder_f((unsigned)(key >> 32));
    }
    __syncthreads();

    if (tid == 0) {
        int nf = 0;
        for (int i = 0; i < T_; i++) {
            int j = argj[i];
            if (p[j] < 0) { p[j] = i; rowmatch[i] = 1; }
            else { rowmatch[i] = 0; flist[nf++] = i; }
        }
        nfree_s = nf;
        inext_s = nf > 0 ? flist[0] : -1;
    }

    // ---- Phase 0.5: augmenting row reduction (2 barriers per scan) ----
    {
        int fpos = 1;                  // meaningful on tid0 only
        int scans = 0;
        while (scans < 400) {
            __syncthreads();           // publish inext_s / p / rowmatch writes
            int i = inext_s;
            if (i < 0) break;
            const float* row = cost + (size_t)i * Q_;

            // per-thread two smallest over its 2 columns
            float c0 = __ldg(row + tid) - vreg[0];
            unsigned o0 = order_f(c0);
            unsigned o1 = 0xFFFFFFFFu;
            int j2 = tid + NTH;
            if (j2 < Q_) o1 = order_f(__ldg(row + j2) - vreg[1]);

            unsigned lo, hi, bj;
            if (o0 <= o1) { lo = o0; hi = o1; bj = (unsigned)tid; }
            else          { lo = o1; hi = o0; bj = (unsigned)j2; }

            unsigned m1w = __reduce_min_sync(0xFFFFFFFFu, lo);
            unsigned ball = __ballot_sync(0xFFFFFFFFu, lo == m1w);
            unsigned jc = (lo == m1w) ? bj : 0xFFFFFFFFu;
            unsigned j1w = __reduce_min_sync(0xFFFFFFFFu, jc);
            unsigned m2c = (lo == m1w) ? hi : lo;
            unsigned m2w = __reduce_min_sync(0xFFFFFFFFu, m2c);
            if (__popc(ball) > 1) m2w = m1w;

            if (lane == 0) {
                wred[0][wid] = ((unsigned long long)m1w << 32) | j1w;
                wred2[wid] = m2w;
            }
            __syncthreads();

            // all threads: global (m1, j1, m2)
            unsigned long long tot = tree_min16(wred[0]);
            int j1 = (int)(tot & 0xFFFFFFFFu);
            unsigned m1o = (unsigned)(tot >> 32);
            unsigned m2o = 0xFFFFFFFFu;
            int cnt = 0;
            #pragma unroll
            for (int w = 0; w < NW; w++) {
                unsigned mw = (unsigned)(wred[0][w] >> 32);
                if (mw == m1o) {
                    cnt++;
                    unsigned x = wred2[w];
                    if (x < m2o) m2o = x;
                } else if (mw < m2o) {
                    m2o = mw;
                }
            }
            if (cnt > 1) m2o = m1o;

            // unconditional column-dual fix: no-op when the scan doesn't take
            float d = unorder_f(m2o) - unorder_f(m1o);
            if ((j1 & (NTH - 1)) == tid) vreg[j1 >> 9] -= d;

            if (tid == 0) {            // only tid0 touches p -> race-free
                int iold = p[j1];
                bool take = (iold < 0) || (m1o < m2o);
                u[i] = unorder_f(m2o);
                int nx = -1;
                if (take) {
                    p[j1] = i;
                    rowmatch[i] = 1;
                    if (iold >= 0) { rowmatch[iold] = 0; nx = iold; }
                }
                if (nx < 0 && fpos < nfree_s) nx = flist[fpos++];
                inext_s = nx;
            }
            scans++;
        }
        __syncthreads();
    }

    // ---- Phase 1: shortest augmenting path for remaining unmatched rows ----
    for (int i = 0; i < T_; i++) {
        if (rowmatch[i]) continue;

        unsigned minv[K_];                 // ordered-uint shortest-path dist
        unsigned um = 0;
        #pragma unroll
        for (int k = 0; k < K_; k++) {
            minv[k] = 0xFFFFFFFEu;
            if (tid + k * NTH >= Q_) um |= (1u << k);
        }

        int j0 = Q_;
        int i0 = i;
        float shift = 0.f;
        int iter = 0;
        int j1;
        float Sf;

        while (true) {
            float base = shift - u[i0];
            const float* row = cost + (size_t)i0 * Q_;

            unsigned bo = 0xFFFFFFFFu, bj = 0xFFFFFFFFu;
            #pragma unroll
            for (int k = 0; k < K_; k++) {
                int j = tid + k * NTH;
                if (!((um >> k) & 1u)) {
                    unsigned co = order_f(__ldg(row + j) - vreg[k] + base);
                    if (co < minv[k]) { minv[k] = co; sway[j] = j0; }
                    if (minv[k] < bo) { bo = minv[k]; bj = (unsigned)j; }
                }
            }
            unsigned m = __reduce_min_sync(0xFFFFFFFFu, bo);
            unsigned jc = (bo == m) ? bj : 0xFFFFFFFFu;
            unsigned jm = __reduce_min_sync(0xFFFFFFFFu, jc);

            int buf = iter & 1;
            if (lane == 0)
                wred[buf][wid] = ((unsigned long long)m << 32) | jm;
            __syncthreads();

            unsigned long long tot = tree_min16(wred[buf]);
            j1 = (int)(tot & 0xFFFFFFFFu);
            Sf = unorder_f((unsigned)(tot >> 32));

            int i0n = p[j1];
            if (i0n < 0) break;

            if ((j1 & (NTH - 1)) == tid) um |= (1u << (j1 >> 9));
            j0 = j1;
            i0 = i0n;
            shift = Sf;
            iter++;
        }

        // deferred dual updates
        #pragma unroll
        for (int k = 0; k < K_; k++) {
            int j = tid + k * NTH;
            if (j < Q_ && ((um >> k) & 1u)) {
                float diff = Sf - unorder_f(minv[k]);
                vreg[k] -= diff;
                u[p[j]] += diff;
            }
        }
        if (tid == 0) u[i] += Sf;
        __syncthreads();

        if (tid == 0) {
            int j = j1;
            while (j != Q_) {
                int jn = sway[j];
                p[j] = (jn == Q_) ? i : p[jn];
                j = jn;
            }
            rowmatch[i] = 1;
        }
        __syncthreads();
    }

    // write indices sorted by query (rank via counting)
    for (int j = tid; j < Q_; j += NTH) {
        int r = p[j];
        if (r >= 0) colarr[r] = j;
    }
    __syncthreads();

    if (writeIdx) {
        float* oidx = out + (size_t)B_ * Q_ * T_;
        if (tid < T_) {
            int c = colarr[tid];
            int rank = 0;
            for (int s = 0; s < T_; s++) rank += (colarr[s] < c);
            oidx[(size_t)b * T_ + rank] = (float)c;                      // pred_idx
            oidx[(size_t)B_ * T_ + (size_t)b * T_ + rank] = (float)tid;  // tgt_idx
        }
    }

    // reset rowmin identity for the next graph replay
    if (tid < T_) g_rowmin[b * T_ + tid] = 0ull;
}

// ---------------------------------------------------------------------------
extern "C" void kernel_launch(void* const* d_in, const int* in_sizes, int n_in,
                              void* d_out, int out_size) {
    const float* logits = (const float*)d_in[0];
    const float* pboxes = (const float*)d_in[1];
    const int*   labels = (const int*)d_in[2];
    const float* tboxes = (const float*)d_in[3];
    float* out = (float*)d_out;

    dim3 tg((Q_ + 31) / 32, B_);
    cost_fused_kernel<<<tg, NTC>>>(logits, pboxes, labels, tboxes, out);

    int writeIdx = (out_size >= (int)((long long)B_ * Q_ * T_ + 2LL * B_ * T_)) ? 1 : 0;
    hungarian_kernel<<<B_, NTH>>>(out, writeIdx);
}

// round 11
// speedup vs baseline: 1.1761x; 1.0486x over previous
#include <cuda_runtime.h>
#include <cstdint>

#define B_ 64
#define Q_ 900
#define T_ 100
#define C_ 256
#define NTC 256          // cost kernel block
#define NTH 256          // hungarian block (8 warps: 4 matched + 4 free)
#define NCAND 128

// Scratch: transposed cost [B, T, Q] so hungarian reads contiguous rows.
__device__ float g_costT[(size_t)B_ * T_ * Q_];
// Per-(b,t) ~packed row-min key; 0 (static init) is the identity for atomicMax.
__device__ unsigned long long g_rowmin[B_ * T_];   // zero-initialized
// Per-row bottom-[100,128] candidate keys (order(c)<<32 | j), unsorted.
__device__ unsigned long long g_cand[(size_t)B_ * T_ * NCAND];
__device__ int g_ncand[B_ * T_];

__device__ __forceinline__ unsigned order_f(float f) {
    unsigned o = __float_as_uint(f);
    return (o & 0x80000000u) ? ~o : (o | 0x80000000u);
}
__device__ __forceinline__ float unorder_f(unsigned o) {
    return __uint_as_float((o & 0x80000000u) ? (o ^ 0x80000000u) : ~o);
}

// ---------------------------------------------------------------------------
// Kernel 1 (R9 version, known-good): one block per (b, 32-query tile).
// Label-sorted target order makes the logits gather semi-coalesced.
// ---------------------------------------------------------------------------
__global__ void __launch_bounds__(NTC) cost_fused_kernel(
        const float* __restrict__ logits,
        const float* __restrict__ pboxes,
        const int* __restrict__ labels,
        const float* __restrict__ tboxes,
        float* __restrict__ out) {
    __shared__ int    lab_s[T_];
    __shared__ int    ord_s[T_];
    __shared__ float4 tb_s[T_];       // cxcywh
    __shared__ float4 te_s[T_];       // xyxy
    __shared__ float  ta_s[T_];       // area
    __shared__ float4 pb_s[32];
    __shared__ float  tile[32][101];

    int b = blockIdx.y;
    int q0 = blockIdx.x * 32;
    int tid = threadIdx.x;

    if (tid < T_) {
        lab_s[tid] = labels[b * T_ + tid];
        float4 tb = __ldg(&((const float4*)tboxes)[b * T_ + tid]);
        tb_s[tid] = tb;
        float4 te;
        te.x = tb.x - 0.5f * tb.z; te.y = tb.y - 0.5f * tb.w;
        te.z = tb.x + 0.5f * tb.z; te.w = tb.y + 0.5f * tb.w;
        te_s[tid] = te;
        ta_s[tid] = (te.z - te.x) * (te.w - te.y);
    }
    if (tid < 32 && q0 + tid < Q_)
        pb_s[tid] = __ldg(&((const float4*)pboxes)[b * Q_ + q0 + tid]);
    __syncthreads();

    if (tid < T_) {                   // rank sort by (label, index)
        int lab = lab_s[tid];
        int rank = 0;
        for (int s = 0; s < T_; s++) {
            int ls = lab_s[s];
            rank += (ls < lab) || (ls == lab && s < tid);
        }
        ord_s[rank] = tid;
    }
    __syncthreads();

    int qq = tid >> 3;
    int q = q0 + qq;
    int t_lo = tid & 7;
    if (q < Q_) {
        float4 pb = pb_s[qq];
        float ax0 = pb.x - 0.5f * pb.z, ay0 = pb.y - 0.5f * pb.w;
        float ax1 = pb.x + 0.5f * pb.z, ay1 = pb.y + 0.5f * pb.w;
        float areaA = (ax1 - ax0) * (ay1 - ay0);
        const float* lrow = logits + ((long long)b * Q_ + q) * C_;

        #pragma unroll
        for (int s = 0; s < 13; s++) {
            int sidx = t_lo + (s << 3);
            if (sidx >= T_) break;
            int tt = ord_s[sidx];

            float cc = -__ldg(lrow + lab_s[tt]);
            float4 tb = tb_s[tt];
            float4 te = te_s[tt];

            float cb = fabsf(pb.x - tb.x) + fabsf(pb.y - tb.y);
            cb += fabsf(pb.z - tb.z);
            cb += fabsf(pb.w - tb.w);

            float wx = fminf(ax1, te.z) - fmaxf(ax0, te.x); wx = fmaxf(wx, 0.f);
            float wy = fminf(ay1, te.w) - fmaxf(ay0, te.y); wy = fmaxf(wy, 0.f);
            float inter = wx * wy;
            float uni = areaA + ta_s[tt] - inter;
            float iou = __fdividef(inter, uni);
            float ex = fmaxf(ax1, te.z) - fminf(ax0, te.x); ex = fmaxf(ex, 0.f);
            float ey = fmaxf(ay1, te.w) - fminf(ay0, te.y); ey = fmaxf(ey, 0.f);
            float enc = ex * ey;
            float giou = iou - __fdividef(enc - uni, enc);

            tile[qq][tt] = (cc + cb) - giou;
        }
    }
    __syncthreads();

    for (int idx = tid; idx < 32 * T_; idx += NTC) {
        int qq2 = idx / T_, tt = idx - qq2 * T_;
        int q2 = q0 + qq2;
        if (q2 < Q_)
            out[((size_t)b * Q_ + q2) * T_ + tt] = tile[qq2][tt];
    }
    for (int idx = tid; idx < 32 * T_; idx += NTC) {
        int tt = idx >> 5, q2 = q0 + (idx & 31);
        if (q2 < Q_)
            g_costT[((size_t)b * T_ + tt) * Q_ + q2] = tile[idx & 31][tt];
    }
    if (tid < T_) {
        unsigned long long best = ~0ull;
        int qmax = min(32, Q_ - q0);
        for (int k = 0; k < qmax; k++) {
            unsigned long long key =
                ((unsigned long long)order_f(tile[k][tid]) << 32) | (unsigned)(q0 + k);
            if (key < best) best = key;
        }
        atomicMax(&g_rowmin[b * T_ + tid], ~best);
    }
}

// ---------------------------------------------------------------------------
// Kernel 1.5: per-row bottom-[100,128] candidate selection. One warp per row,
// 29 keys/lane in registers, binary search on the ordered value, exact
// lowest-j refinement on value ties. Superset of bottom-100 by (val,j) order.
// ---------------------------------------------------------------------------
__global__ void __launch_bounds__(256) cand_kernel() {
    int gw = (blockIdx.x * 256 + threadIdx.x) >> 5;    // row id = b*T + t
    int lane = threadIdx.x & 31;
    if (gw >= B_ * T_) return;
    const float* row = g_costT + (size_t)gw * Q_;

    unsigned long long key[29];
    #pragma unroll
    for (int k = 0; k < 29; k++) {
        int j = lane + (k << 5);
        key[k] = (j < Q_)
          ? (((unsigned long long)order_f(__ldg(row + j)) << 32) | (unsigned)j)
          : ~0ull;
    }

    // binary search on value for count(val<=tau) in [100,128]
    unsigned lo = 0, hi = 0xFFFFFFFFu;
    unsigned tau = 0; int n = -1;
    for (int it = 0; it < 34 && n < 0; it++) {
        unsigned mid = (it < 32) ? (lo + ((hi - lo) >> 1)) : hi;
        int c = 0;
        #pragma unroll
        for (int k = 0; k < 29; k++)
            c += ((unsigned)(key[k] >> 32) <= mid) ? 1 : 0;
        c = __reduce_add_sync(0xFFFFFFFFu, c);
        if (c >= 100 && c <= NCAND) { tau = mid; n = c; }
        else if (c > NCAND) hi = mid;
        else lo = mid + 1;
        if (lo >= hi && it < 32) { /* converged; final probe at it>=32 */ }
    }

    bool tie = false; unsigned jcut = 0;
    if (n < 0) {                       // value tie group straddles [100,128]
        tau = hi;
        int n1 = 0;
        #pragma unroll
        for (int k = 0; k < 29; k++)
            n1 += ((unsigned)(key[k] >> 32) < tau) ? 1 : 0;
        n1 = __reduce_add_sync(0xFFFFFFFFu, n1);
        int need = 100 - n1;           // >= 1
        unsigned jlo = 0, jhi = 1023;
        for (int it = 0; it < 10; it++) {
            unsigned jm = (jlo + jhi) >> 1;
            int c = 0;
            #pragma unroll
            for (int k = 0; k < 29; k++) {
                unsigned v = (unsigned)(key[k] >> 32);
                unsigned j = (unsigned)(key[k] & 0xFFFFFFFFu);
                c += (v == tau && j <= jm) ? 1 : 0;
            }
            c = __reduce_add_sync(0xFFFFFFFFu, c);
            if (c >= need) jhi = jm; else jlo = jm + 1;
        }
        jcut = jhi; tie = true;
    }

    // compact qualifying keys (unsorted set)
    unsigned long long* dst = g_cand + ((size_t)gw << 7);
    int base = 0;
    #pragma unroll
    for (int k = 0; k < 29; k++) {
        unsigned v = (unsigned)(key[k] >> 32);
        unsigned j = (unsigned)(key[k] & 0xFFFFFFFFu);
        bool qv = tie ? ((v < tau) || (v == tau && j <= jcut)) : (v <= tau);
        qv = qv && (j < (unsigned)Q_);
        unsigned mask = __ballot_sync(0xFFFFFFFFu, qv);
        if (qv) dst[base + __popc(mask & ((1u << lane) - 1))] = key[k];
        base += __popc(mask);
    }
    if (lane == 0) g_ncand[gw] = base;
}

// ---------------------------------------------------------------------------
// Kernel 2: JV, greedy rowmin init + matched/free-split SAP.
// Warps 0-3: one matched column per thread, state in registers.
// Warps 4-7: probe the current row's candidate list for the free minimum.
// ---------------------------------------------------------------------------
__global__ void __launch_bounds__(NTH) hungarian_kernel(float* __restrict__ out,
                                                        int writeIdx) {
    int b = blockIdx.x;
    const float* cost = g_costT + (size_t)b * T_ * Q_;

    __shared__ float u[T_ + 1];
    __shared__ int p[Q_];
    __shared__ int sway[Q_];
    __shared__ unsigned long long keybuf[2][8];
    __shared__ int mlist[T_];
    __shared__ int ncand_s[T_];
    __shared__ int argj[T_];
    __shared__ int rowmatch[T_];
    __shared__ int colarr[T_];
    __shared__ int nm_s;

    int tid = threadIdx.x, lane = tid & 31, wid = tid >> 5;

    for (int j = tid; j < Q_; j += NTH) p[j] = -1;
    if (tid < T_) {
        unsigned long long k = ~g_rowmin[b * T_ + tid];
        argj[tid] = (int)(k & 0xFFFFFFFFu);
        u[tid] = unorder_f((unsigned)(k >> 32));
        ncand_s[tid] = g_ncand[b * T_ + tid];
    }
    if (tid == 0) u[T_] = 0.f;
    __syncthreads();

    if (tid == 0) {
        int nm = 0;
        for (int i = 0; i < T_; i++) {
            int j = argj[i];
            if (p[j] < 0) { p[j] = i; rowmatch[i] = 1; mlist[nm++] = j; }
            else rowmatch[i] = 0;
        }
        nm_s = nm;
    }
    __syncthreads();

    // per-slot matched-column registers (slot = tid, threads 0..127)
    int myj = -1;
    float myv = 0.f;
    unsigned myminv = ~0u;
    bool myused = false;

    for (int i = 0; i < T_; i++) {
        if (rowmatch[i]) continue;
        int nm = nm_s;
        if (tid < nm && myj < 0) { myj = mlist[tid]; myv = 0.f; }
        myminv = 0xFFFFFFFEu; myused = false;
        unsigned long long freebest = ~0ull;
        int freepred = Q_;

        int j0 = Q_, i0 = i, iter = 0, j1;
        float shift = 0.f, Sf;

        while (true) {
            float base = shift - u[i0];
            unsigned bo = 0xFFFFFFFFu, bj = 0xFFFFFFFFu;
            if (tid < 128) {                          // matched side
                if (tid < nm && !myused) {
                    float cur = __ldg(cost + (size_t)i0 * Q_ + myj) - myv + base;
                    unsigned co = order_f(cur);
                    if (co < myminv) { myminv = co; sway[myj] = j0; }
                    bo = myminv; bj = (unsigned)myj;
                }
            } else {                                  // free side (candidates)
                int ci = tid - 128;
                if (ci < ncand_s[i0]) {
                    unsigned long long ck =
                        __ldg(&g_cand[((size_t)(b * T_ + i0) << 7) + ci]);
                    int j = (int)(ck & 0xFFFFFFFFu);
                    if (p[j] < 0) {
                        float val = unorder_f((unsigned)(ck >> 32)) + base;
                        bo = order_f(val); bj = (unsigned)j;
                    }
                }
            }
            unsigned m = __reduce_min_sync(0xFFFFFFFFu, bo);
            unsigned jc = (bo == m) ? bj : 0xFFFFFFFFu;
            unsigned jm = __reduce_min_sync(0xFFFFFFFFu, jc);
            int buf = iter & 1;
            if (lane == 0) keybuf[buf][wid] = ((unsigned long long)m << 32) | jm;
            __syncthreads();

            const unsigned long long* kb = keybuf[buf];
            unsigned long long m0 = kb[0] < kb[2] ? kb[0] : kb[2];
            unsigned long long m1 = kb[1] < kb[3] ? kb[1] : kb[3];
            unsigned long long mpart = m0 < m1 ? m0 : m1;
            unsigned long long f0 = kb[4] < kb[6] ? kb[4] : kb[6];
            unsigned long long f1 = kb[5] < kb[7] ? kb[5] : kb[7];
            unsigned long long fpart = f0 < f1 ? f0 : f1;
            if (fpart < freebest) { freebest = fpart; freepred = j0; }
            unsigned long long tot = mpart < freebest ? mpart : freebest;
            j1 = (int)(tot & 0xFFFFFFFFu);
            Sf = unorder_f((unsigned)(tot >> 32));

            int i0n = p[j1];
            if (i0n < 0) break;                       // free column -> augment

            if (myj == j1) myused = true;             // owner freezes its dist
            j0 = j1; i0 = i0n; shift = Sf; iter++;
        }

        // deferred dual updates (used matched columns only; free v stays 0)
        if (tid < nm && myused) {
            float diff = Sf - unorder_f(myminv);
            myv -= diff;
            u[p[myj]] += diff;                        // rows distinct
        }
        if (tid == 0) u[i] += Sf;
        __syncthreads();                              // duals read p pre-augment

        if (tid == 0) {
            sway[j1] = freepred;
            int j = j1;
            while (j != Q_) {
                int jn = sway[j];
                p[j] = (jn == Q_) ? i : p[jn];
                j = jn;
            }
            rowmatch[i] = 1;
            mlist[nm_s] = j1;                         // new matched column
            nm_s = nm_s + 1;
        }
        __syncthreads();
    }

    // write indices sorted by query (rank via counting)
    for (int j = tid; j < Q_; j += NTH) {
        int r = p[j];
        if (r >= 0) colarr[r] = j;
    }
    __syncthreads();

    if (writeIdx) {
        float* oidx = out + (size_t)B_ * Q_ * T_;
        if (tid < T_) {
            int c = colarr[tid];
            int rank = 0;
            for (int s = 0; s < T_; s++) rank += (colarr[s] < c);
            oidx[(size_t)b * T_ + rank] = (float)c;                      // pred_idx
            oidx[(size_t)B_ * T_ + (size_t)b * T_ + rank] = (float)tid;  // tgt_idx
        }
    }

    // reset rowmin identity for the next graph replay
    if (tid < T_) g_rowmin[b * T_ + tid] = 0ull;
}

// ---------------------------------------------------------------------------
extern "C" void kernel_launch(void* const* d_in, const int* in_sizes, int n_in,
                              void* d_out, int out_size) {
    const float* logits = (const float*)d_in[0];
    const float* pboxes = (const float*)d_in[1];
    const int*   labels = (const int*)d_in[2];
    const float* tboxes = (const float*)d_in[3];
    float* out = (float*)d_out;

    dim3 tg((Q_ + 31) / 32, B_);
    cost_fused_kernel<<<tg, NTC>>>(logits, pboxes, labels, tboxes, out);

    int nrows = B_ * T_;
    cand_kernel<<<(nrows * 32 + 255) / 256, 256>>>();

    int writeIdx = (out_size >= (int)((long long)B_ * Q_ * T_ + 2LL * B_ * T_)) ? 1 : 0;
    hungarian_kernel<<<B_, NTH>>>(out, writeIdx);
}